// round 1
// baseline (speedup 1.0000x reference)
#include <cuda_runtime.h>
#include <cuda_bf16.h>

// Problem constants
#define BATCH 16
#define SEQ   4096
#define HDIM  1024
#define HN    16      // heads
#define HD    64      // head dim

// ---------------------------------------------------------------------------
// Scratch (device globals: no allocation allowed)
// ---------------------------------------------------------------------------
__device__ float g_q[BATCH * HDIM];         // q = query @ Wq^T + bq
__device__ float g_w[BATCH * HN * HDIM];    // w[b,h,:] = (1/32) Wk_h^T q_h
__device__ float g_c[BATCH * HN];           // score bias const (1/32) q_h . bk_h
__device__ float g_u[BATCH * HN * HDIM];    // u[b,h,:] = sum_s att * value_row
__device__ float g_A[BATCH * HN];           // A[b,h]   = sum_s att
__device__ float g_o1[BATCH * HDIM];        // out before final projection

// ---------------------------------------------------------------------------
// f32x2 helpers (packed FFMA2 — 2x fp32 throughput, only reachable via PTX)
// ---------------------------------------------------------------------------
__device__ __forceinline__ void fma2(unsigned long long &d,
                                     unsigned long long a,
                                     unsigned long long b) {
    asm("fma.rn.f32x2 %0, %1, %2, %0;" : "+l"(d) : "l"(a), "l"(b));
}
__device__ __forceinline__ float2 unpack2(unsigned long long v) {
    float2 f;
    asm("mov.b64 {%0, %1}, %2;" : "=f"(f.x), "=f"(f.y) : "l"(v));
    return f;
}
__device__ __forceinline__ unsigned long long pack_dup(float a) {
    unsigned long long r;
    asm("mov.b64 %0, {%1, %1};" : "=l"(r) : "f"(a));
    return r;
}

// ---------------------------------------------------------------------------
// K0: zero the accumulators
// ---------------------------------------------------------------------------
__global__ void k0_zero() {
    int i = blockIdx.x * blockDim.x + threadIdx.x;
    if (i < BATCH * HN * HDIM) g_u[i] = 0.f;
    if (i < BATCH * HN)        g_A[i] = 0.f;
}

// ---------------------------------------------------------------------------
// K1: q[b,i] = query[b,:] . Wq[i,:] + bq[i]   (warp per output)
// ---------------------------------------------------------------------------
__global__ void k1_q(const float* __restrict__ query,
                     const float* __restrict__ Wq,
                     const float* __restrict__ bq) {
    int gw   = (blockIdx.x * blockDim.x + threadIdx.x) >> 5;
    int lane = threadIdx.x & 31;
    if (gw >= BATCH * HDIM) return;
    int b = gw >> 10, i = gw & 1023;
    const float4* qr = (const float4*)(query + b * HDIM);
    const float4* wr = (const float4*)(Wq + (size_t)i * HDIM);
    float acc = 0.f;
#pragma unroll
    for (int t = 0; t < 8; t++) {
        float4 a = qr[t * 32 + lane];
        float4 w = wr[t * 32 + lane];
        acc += a.x * w.x + a.y * w.y + a.z * w.z + a.w * w.w;
    }
#pragma unroll
    for (int o = 16; o > 0; o >>= 1) acc += __shfl_xor_sync(~0u, acc, o);
    if (lane == 0) g_q[gw] = acc + bq[i];
}

// ---------------------------------------------------------------------------
// K2: w[b,h,j] = (1/32) sum_d q[b,h*64+d] * Wk[h*64+d, j]
//     c[b,h]   = (1/32) sum_d q[b,h*64+d] * bk[h*64+d]
// block per (h,b) (h-major for L2 reuse of Wk rows), 256 threads.
// ---------------------------------------------------------------------------
__global__ void k2_w(const float* __restrict__ Wk,
                     const float* __restrict__ bk) {
    int h = blockIdx.x >> 4;
    int b = blockIdx.x & 15;
    __shared__ float qh[HD];
    int tid = threadIdx.x;
    if (tid < HD) qh[tid] = g_q[b * HDIM + h * HD + tid];
    __syncthreads();

    float4 acc = make_float4(0.f, 0.f, 0.f, 0.f);
    const float4* wk = (const float4*)(Wk + (size_t)(h * HD) * HDIM) + tid;
#pragma unroll 8
    for (int d = 0; d < HD; d++) {
        float4 v = wk[d * 256];
        float  s = qh[d];
        acc.x += s * v.x; acc.y += s * v.y; acc.z += s * v.z; acc.w += s * v.w;
    }
    const float scale = 0.03125f;  // 1/sqrt(1024)
    acc.x *= scale; acc.y *= scale; acc.z *= scale; acc.w *= scale;
    ((float4*)(g_w + (b * HN + h) * HDIM))[tid] = acc;

    if (tid == 0) {
        float cc = 0.f;
        for (int d = 0; d < HD; d++) cc += qh[d] * bk[h * HD + d];
        g_c[b * HN + h] = cc * scale;
    }
}

// ---------------------------------------------------------------------------
// K3: the streaming kernel.
//  grid (16 chunks, 16 batches), 256 threads (8 warps), 2 CTA/SM -> 1 wave.
//  Per group of 8 rows: warp wq computes scores+softmax for row (g*8+wq)
//  with w resident in smem (f32x2 FMAs), writes packed att{a,a} to smem;
//  then all 8 warps accumulate u over the 8 rows, each warp owning a 128-j
//  slice with register-resident f32x2 accumulators. Atomic flush at the end.
// ---------------------------------------------------------------------------
__global__ __launch_bounds__(256, 2)
void k3_attend(const float* __restrict__ key,
               const float* __restrict__ value) {
    extern __shared__ float smem_raw[];
    unsigned long long* att_s = (unsigned long long*)smem_raw;       // [8][16] packed {a,a}
    float* c_s = (float*)(att_s + 8 * HN);                           // 16 floats
    float* w_s = c_s + 16;                                           // 16384 floats (offset 1088B, 16B aligned)

    const int b     = blockIdx.y;
    const int chunk = blockIdx.x;
    const int tid   = threadIdx.x;
    const int wq    = tid >> 5;
    const int lane  = tid & 31;

    // stage w[b] into smem
    {
        const float4* src = (const float4*)(g_w + b * HN * HDIM);
        float4* dst = (float4*)w_s;
        for (int i = tid; i < HN * HDIM / 4; i += 256) dst[i] = src[i];
        if (tid < HN) c_s[tid] = g_c[b * HN + tid];
    }
    __syncthreads();

    // u accumulators: lane owns j0..j0+3 for all 16 heads (f32x2 pairs)
    unsigned long long u2[32];
#pragma unroll
    for (int i = 0; i < 32; i++) u2[i] = 0ULL;
    float a_loc = 0.f;  // threads 0..15 accumulate A[b, tid]

    const int j0 = (wq << 7) + (lane << 2);
    const size_t rowbase = (size_t)b * SEQ * HDIM;
    const float* keyb = key + rowbase;
    const float* valb = value + rowbase;
    const int row0 = chunk << 8;

    for (int g = 0; g < 32; g++) {
        // ---- scores: this warp owns row (row0 + g*8 + wq) ----
        const int srow = row0 + (g << 3) + wq;
        const ulonglong2* kp = (const ulonglong2*)(keyb + (size_t)srow * HDIM);
        unsigned long long p2[HN];
#pragma unroll
        for (int h = 0; h < HN; h++) p2[h] = 0ULL;
#pragma unroll
        for (int kk = 0; kk < 8; kk++) {
            const int jj = (kk << 7) + (lane << 2);
            ulonglong2 kv = kp[jj >> 2];
            const ulonglong2* wp = (const ulonglong2*)w_s + (jj >> 2);
#pragma unroll
            for (int h = 0; h < HN; h++) {
                ulonglong2 wv = wp[h << 8];  // + h*1024 floats
                fma2(p2[h], kv.x, wv.x);
                fma2(p2[h], kv.y, wv.y);
            }
        }
        float p[HN];
#pragma unroll
        for (int h = 0; h < HN; h++) {
            float2 f = unpack2(p2[h]);
            p[h] = f.x + f.y;
        }
#pragma unroll
        for (int h = 0; h < HN; h++) {
            p[h] += __shfl_xor_sync(~0u, p[h], 16);
            p[h] += __shfl_xor_sync(~0u, p[h], 8);
            p[h] += __shfl_xor_sync(~0u, p[h], 4);
            p[h] += __shfl_xor_sync(~0u, p[h], 2);
            p[h] += __shfl_xor_sync(~0u, p[h], 1);
            p[h] += c_s[h];
        }
        // softmax over 16 heads (redundant in all lanes)
        float m = p[0];
#pragma unroll
        for (int h = 1; h < HN; h++) m = fmaxf(m, p[h]);
        float e[HN], sum = 0.f;
#pragma unroll
        for (int h = 0; h < HN; h++) { e[h] = __expf(p[h] - m); sum += e[h]; }
        float inv = __fdividef(1.f, sum);
        if (lane == 0) {
#pragma unroll
            for (int h = 0; h < HN; h++) att_s[wq * HN + h] = pack_dup(e[h] * inv);
        }
        __syncthreads();

        // ---- A accumulation (threads 0..15, one head each) ----
        if (tid < HN) {
            const float* att_f = (const float*)att_s;
#pragma unroll
            for (int r = 0; r < 8; r++) a_loc += att_f[(r * HN + tid) * 2];
        }

        // ---- u accumulation: warp owns j-slice [wq*128, +128) for 8 rows ----
#pragma unroll
        for (int r = 0; r < 8; r++) {
            const int sr = row0 + (g << 3) + r;
            ulonglong2 vv = *(const ulonglong2*)(valb + (size_t)sr * HDIM + j0);
#pragma unroll
            for (int h = 0; h < HN; h++) {
                unsigned long long a2 = att_s[r * HN + h];  // broadcast LDS.64
                fma2(u2[2 * h + 0], a2, vv.x);
                fma2(u2[2 * h + 1], a2, vv.y);
            }
        }
        __syncthreads();
    }

    // flush u partials
    float* ubase = g_u + (b * HN) * HDIM + j0;
#pragma unroll
    for (int h = 0; h < HN; h++) {
        float2 lo = unpack2(u2[2 * h + 0]);
        float2 hi = unpack2(u2[2 * h + 1]);
        atomicAdd(ubase + (h << 10) + 0, lo.x);
        atomicAdd(ubase + (h << 10) + 1, lo.y);
        atomicAdd(ubase + (h << 10) + 2, hi.x);
        atomicAdd(ubase + (h << 10) + 3, hi.y);
    }
    if (tid < HN) atomicAdd(&g_A[b * HN + tid], a_loc);
}

// ---------------------------------------------------------------------------
// K4: out1[b,j] = Wv[j,:] . u[b, j/64, :] + bv[j] * A[b, j/64]
//     warp per j, loop over b (Wv row loaded once into regs).
// ---------------------------------------------------------------------------
__global__ void k4_out(const float* __restrict__ Wv,
                       const float* __restrict__ bv) {
    int gw   = (blockIdx.x * blockDim.x + threadIdx.x) >> 5;
    int lane = threadIdx.x & 31;
    if (gw >= HDIM) return;
    int j = gw, h = j >> 6;
    float4 wvr[8];
    const float4* wr = (const float4*)(Wv + (size_t)j * HDIM);
#pragma unroll
    for (int t = 0; t < 8; t++) wvr[t] = wr[t * 32 + lane];
    float bvj = bv[j];
    for (int b = 0; b < BATCH; b++) {
        const float4* ur = (const float4*)(g_u + (b * HN + h) * HDIM);
        float acc = 0.f;
#pragma unroll
        for (int t = 0; t < 8; t++) {
            float4 uv = ur[t * 32 + lane];
            acc += wvr[t].x * uv.x + wvr[t].y * uv.y + wvr[t].z * uv.z + wvr[t].w * uv.w;
        }
#pragma unroll
        for (int o = 16; o > 0; o >>= 1) acc += __shfl_xor_sync(~0u, acc, o);
        if (lane == 0) g_o1[b * HDIM + j] = acc + bvj * g_A[b * HN + h];
    }
}

// ---------------------------------------------------------------------------
// K5: res[b,i] = Wf[i,:] . out1[b,:] + bf[i]
// ---------------------------------------------------------------------------
__global__ void k5_final(const float* __restrict__ Wf,
                         const float* __restrict__ bf,
                         float* __restrict__ res) {
    int gw   = (blockIdx.x * blockDim.x + threadIdx.x) >> 5;
    int lane = threadIdx.x & 31;
    if (gw >= HDIM) return;
    int i = gw;
    float4 wfr[8];
    const float4* wr = (const float4*)(Wf + (size_t)i * HDIM);
#pragma unroll
    for (int t = 0; t < 8; t++) wfr[t] = wr[t * 32 + lane];
    float bfi = bf[i];
    for (int b = 0; b < BATCH; b++) {
        const float4* orow = (const float4*)(g_o1 + b * HDIM);
        float acc = 0.f;
#pragma unroll
        for (int t = 0; t < 8; t++) {
            float4 ov = orow[t * 32 + lane];
            acc += wfr[t].x * ov.x + wfr[t].y * ov.y + wfr[t].z * ov.z + wfr[t].w * ov.w;
        }
#pragma unroll
        for (int o = 16; o > 0; o >>= 1) acc += __shfl_xor_sync(~0u, acc, o);
        if (lane == 0) res[b * HDIM + i] = acc + bfi;
    }
}

// ---------------------------------------------------------------------------
// launch
// ---------------------------------------------------------------------------
extern "C" void kernel_launch(void* const* d_in, const int* in_sizes, int n_in,
                              void* d_out, int out_size) {
    const float* query = (const float*)d_in[0];
    const float* key_  = (const float*)d_in[1];
    const float* value = (const float*)d_in[2];
    const float* Wq    = (const float*)d_in[3];
    const float* bq    = (const float*)d_in[4];
    const float* Wk    = (const float*)d_in[5];
    const float* bk    = (const float*)d_in[6];
    const float* Wv    = (const float*)d_in[7];
    const float* bv    = (const float*)d_in[8];
    const float* Wf    = (const float*)d_in[9];
    const float* bf    = (const float*)d_in[10];
    float* out = (float*)d_out;

    static bool attr_set = false;
    const int k3_smem = (8 * HN) * 8 + 16 * 4 + HN * HDIM * 4;  // att + c + w = 66624 B
    if (!attr_set) {
        cudaFuncSetAttribute(k3_attend, cudaFuncAttributeMaxDynamicSharedMemorySize, k3_smem);
        attr_set = true;
    }

    k0_zero<<<(BATCH * HN * HDIM + 255) / 256, 256>>>();
    k1_q<<<(BATCH * HDIM * 32 + 255) / 256, 256>>>(query, Wq, bq);
    k2_w<<<HN * BATCH, 256>>>(Wk, bk);
    {
        dim3 grid(SEQ / 256, BATCH);
        k3_attend<<<grid, 256, k3_smem>>>(key_, value);
    }
    k4_out<<<(HDIM * 32 + 255) / 256, 256>>>(Wv, bv);
    k5_final<<<(HDIM * 32 + 255) / 256, 256>>>(Wf, bf, out);
}